// round 5
// baseline (speedup 1.0000x reference)
#include <cuda_runtime.h>
#include <cuda_bf16.h>
#include <cstdint>

#define B_ROWS 16384
#define F_DIM  1024
#define C_COLS 1000
#define C_PAD  1024
#define QSCALE 16.0f                 // pre-quantization scale (per side)
#define INV_QSCALE2 (1.0f / (QSCALE * QSCALE))

// Scratch: normalized, scaled e4m3 operands
__device__ uint8_t g_Fb[(size_t)B_ROWS * F_DIM];   // features, fp8 e4m3 (x16)
__device__ uint8_t g_Pb[(size_t)C_PAD * F_DIM];    // prototypes (padded), fp8 e4m3 (x16)
__device__ float g_rowsum[B_ROWS];

// ---------------------------------------------------------------------------
// Helpers (base-ISA only: cp.async, ldmatrix, fp8 mma.sync — ptxas target is
// plain sm_103, no 'a' features)
// ---------------------------------------------------------------------------
__device__ __forceinline__ uint32_t smem_u32(const void* p) {
    uint32_t a;
    asm("{ .reg .u64 t; cvta.to.shared.u64 t, %1; cvt.u32.u64 %0, t; }" : "=r"(a) : "l"(p));
    return a;
}
__device__ __forceinline__ void cp_async16(uint32_t dst, const void* src) {
    asm volatile("cp.async.cg.shared.global [%0], [%1], 16;" :: "r"(dst), "l"(src));
}
__device__ __forceinline__ void cp_commit() { asm volatile("cp.async.commit_group;" ::: "memory"); }

__device__ __forceinline__ void ldsm_x4(uint32_t& r0, uint32_t& r1, uint32_t& r2, uint32_t& r3,
                                        uint32_t addr) {
    asm volatile("ldmatrix.sync.aligned.m8n8.x4.shared.b16 {%0,%1,%2,%3}, [%4];"
                 : "=r"(r0), "=r"(r1), "=r"(r2), "=r"(r3) : "r"(addr));
}
__device__ __forceinline__ void mma_e4m3(float* c, uint32_t a0, uint32_t a1, uint32_t a2,
                                         uint32_t a3, uint32_t b0, uint32_t b1) {
    asm volatile(
        "mma.sync.aligned.m16n8k32.row.col.f32.e4m3.e4m3.f32 "
        "{%0,%1,%2,%3}, {%4,%5,%6,%7}, {%8,%9}, {%0,%1,%2,%3};"
        : "+f"(c[0]), "+f"(c[1]), "+f"(c[2]), "+f"(c[3])
        : "r"(a0), "r"(a1), "r"(a2), "r"(a3), "r"(b0), "r"(b1));
}
// pack: result<15:8> = cvt(hi), result<7:0> = cvt(lo)
__device__ __forceinline__ uint16_t f2e4m3x2(float hi, float lo) {
    uint16_t r;
    asm("cvt.rn.satfinite.e4m3x2.f32 %0, %1, %2;" : "=h"(r) : "f"(hi), "f"(lo));
    return r;
}

// ---------------------------------------------------------------------------
// Kernels 1/2: L2-normalize rows, scale by 16, -> e4m3
// ---------------------------------------------------------------------------
__global__ void __launch_bounds__(256) norm_features_kernel(const float* __restrict__ in) {
    int row = blockIdx.x, tid = threadIdx.x;
    const float4* rin = (const float4*)(in + (size_t)row * F_DIM);
    float4 v = rin[tid];
    float ss = v.x * v.x + v.y * v.y + v.z * v.z + v.w * v.w;
#pragma unroll
    for (int o = 16; o; o >>= 1) ss += __shfl_xor_sync(0xffffffffu, ss, o);
    __shared__ float red[8];
    if ((tid & 31) == 0) red[tid >> 5] = ss;
    __syncthreads();
    if (tid < 8) {
        float t = red[tid];
#pragma unroll
        for (int o = 4; o; o >>= 1) t += __shfl_xor_sync(0x000000ffu, t, o);
        if (tid == 0) red[0] = t;
    }
    __syncthreads();
    float sc = QSCALE / fmaxf(sqrtf(red[0]), 1e-12f);
    uint32_t w = (uint32_t)f2e4m3x2(v.y * sc, v.x * sc)
               | ((uint32_t)f2e4m3x2(v.w * sc, v.z * sc) << 16);
    ((uint32_t*)g_Fb)[(size_t)row * 256 + tid] = w;
    if (tid == 0) g_rowsum[row] = 0.0f;
}

__global__ void __launch_bounds__(256) norm_protos_kernel(const float* __restrict__ in) {
    int row = blockIdx.x, tid = threadIdx.x;
    uint32_t* dst = (uint32_t*)g_Pb + (size_t)row * 256;
    if (row >= C_COLS) { dst[tid] = 0u; return; }
    const float4* rin = (const float4*)(in + (size_t)row * F_DIM);
    float4 v = rin[tid];
    float ss = v.x * v.x + v.y * v.y + v.z * v.z + v.w * v.w;
#pragma unroll
    for (int o = 16; o; o >>= 1) ss += __shfl_xor_sync(0xffffffffu, ss, o);
    __shared__ float red[8];
    if ((tid & 31) == 0) red[tid >> 5] = ss;
    __syncthreads();
    if (tid < 8) {
        float t = red[tid];
#pragma unroll
        for (int o = 4; o; o >>= 1) t += __shfl_xor_sync(0x000000ffu, t, o);
        if (tid == 0) red[0] = t;
    }
    __syncthreads();
    float sc = QSCALE / fmaxf(sqrtf(red[0]), 1e-12f);
    dst[tid] = (uint32_t)f2e4m3x2(v.y * sc, v.x * sc)
             | ((uint32_t)f2e4m3x2(v.w * sc, v.z * sc) << 16);
}

// ---------------------------------------------------------------------------
// Kernel 3: fp8 e4m3 mma.sync GEMM, CTA 128x128, BK=128 fp8, 2-stage pipeline
// 72KB smem -> 2 CTAs/SM (16 warps/SM).
// 8 warps: wm = wid>>2 (0..1, 64 rows each), wn = wid&3 (0..3, 32 cols each)
// Epilogue: sim = c/256; iso = |ds| * sqrt(max(1 - sim, 0)); store + atomics
// ---------------------------------------------------------------------------
#define STAGES 2
#define BK 128                        // fp8 elements per chunk (128 bytes/row)
#define KCHUNKS (F_DIM / BK)          // 8
#define PAD_BYTES 144                 // 128B data + 16B pad per row
#define A_ST_BYTES (128 * PAD_BYTES)  // 18432
#define STAGE_BYTES (2 * A_ST_BYTES)  // 36864 (A then B)
#define GEMM_SMEM (STAGES * STAGE_BYTES)   // 73728

__device__ __forceinline__ void load_tile(uint32_t base, int kc, int m0, int n0, int tid) {
    const char* fb = (const char*)g_Fb;
    const char* pb = (const char*)g_Pb;
    uint32_t st = base + (uint32_t)(kc & (STAGES - 1)) * STAGE_BYTES;
#pragma unroll
    for (int it = 0; it < 4; it++) {
        int s = tid + it * 256;            // 0..1023
        int r = s >> 3, q = s & 7;
        cp_async16(st + (uint32_t)(r * PAD_BYTES + q * 16),
                   fb + (size_t)(m0 + r) * 1024 + (size_t)kc * 128 + q * 16);
    }
    uint32_t stB = st + A_ST_BYTES;
#pragma unroll
    for (int it = 0; it < 4; it++) {
        int s = tid + it * 256;
        int r = s >> 3, q = s & 7;
        cp_async16(stB + (uint32_t)(r * PAD_BYTES + q * 16),
                   pb + (size_t)(n0 + r) * 1024 + (size_t)kc * 128 + q * 16);
    }
    cp_commit();
}

__global__ void __launch_bounds__(256, 2) gemm_kernel(const float* __restrict__ ds,
                                                      float* __restrict__ out) {
    extern __shared__ char smem_raw[];
    uint32_t base = smem_u32(smem_raw);

    int tid = threadIdx.x;
    int wid = tid >> 5, l = tid & 31;
    int wm = wid >> 2, wn = wid & 3;
    int m0 = blockIdx.y * 128, n0 = blockIdx.x * 128;

    float c[4][4][4];
#pragma unroll
    for (int i = 0; i < 4; i++)
#pragma unroll
        for (int j = 0; j < 4; j++)
#pragma unroll
            for (int k = 0; k < 4; k++) c[i][j][k] = 0.0f;

    // prologue: prefetch chunk 0
    load_tile(base, 0, m0, n0, tid);

    for (int kc = 0; kc < KCHUNKS; kc++) {
        asm volatile("cp.async.wait_group 0;" ::: "memory");
        __syncthreads();

        int j = kc + 1;
        if (j < KCHUNKS) load_tile(base, j, m0, n0, tid);

        uint32_t st = base + (uint32_t)(kc & (STAGES - 1)) * STAGE_BYTES;
        uint32_t aBase = st + (uint32_t)(wm * 64) * PAD_BYTES;
        uint32_t bBase = st + A_ST_BYTES + (uint32_t)(wn * 32) * PAD_BYTES;

        int g = l >> 3;          // 0..3
        int r8 = l & 7;
        // each ks covers 32 fp8 of K = 32 bytes
#pragma unroll
        for (int ks = 0; ks < 4; ks++) {
            uint32_t a[4][4];
#pragma unroll
            for (int mt = 0; mt < 4; mt++) {
                // matrices: g0 rows 0-7 kB0 | g1 rows 8-15 kB0 | g2 rows 0-7 kB16 | g3 rows 8-15 kB16
                uint32_t addr = aBase + (uint32_t)((mt * 16 + (g & 1) * 8 + r8) * PAD_BYTES
                                                  + ks * 32 + (g >> 1) * 16);
                ldsm_x4(a[mt][0], a[mt][1], a[mt][2], a[mt][3], addr);
            }
            uint32_t b[4][2];
#pragma unroll
            for (int pair = 0; pair < 2; pair++) {
                // matrices: [ntile 2p, k-lo] [ntile 2p, k-hi] [ntile 2p+1, k-lo] [ntile 2p+1, k-hi]
                int ntile = pair * 2 + (g >> 1);
                uint32_t addr = bBase + (uint32_t)((ntile * 8 + r8) * PAD_BYTES
                                                  + ks * 32 + (g & 1) * 16);
                ldsm_x4(b[pair * 2][0], b[pair * 2][1], b[pair * 2 + 1][0], b[pair * 2 + 1][1], addr);
            }
#pragma unroll
            for (int mt = 0; mt < 4; mt++)
#pragma unroll
                for (int nt = 0; nt < 4; nt++)
                    mma_e4m3(c[mt][nt], a[mt][0], a[mt][1], a[mt][2], a[mt][3],
                             b[nt][0], b[nt][1]);
        }
        __syncthreads();
    }

    // ---------------- epilogue ----------------
    float dsa = fabsf(ds[0]);
    float rs[4][2];
#pragma unroll
    for (int mt = 0; mt < 4; mt++) { rs[mt][0] = 0.0f; rs[mt][1] = 0.0f; }

#pragma unroll
    for (int mt = 0; mt < 4; mt++) {
        int mrow = m0 + wm * 64 + mt * 16 + (l >> 2);
#pragma unroll
        for (int nt = 0; nt < 4; nt++) {
            int col = n0 + wn * 32 + nt * 8 + 2 * (l & 3);
            float i0 = dsa * sqrtf(fmaxf(1.0f - c[mt][nt][0] * INV_QSCALE2, 0.0f));
            float i1 = dsa * sqrtf(fmaxf(1.0f - c[mt][nt][1] * INV_QSCALE2, 0.0f));
            float i2 = dsa * sqrtf(fmaxf(1.0f - c[mt][nt][2] * INV_QSCALE2, 0.0f));
            float i3 = dsa * sqrtf(fmaxf(1.0f - c[mt][nt][3] * INV_QSCALE2, 0.0f));
            if (col < C_COLS) {             // col even, C_COLS even -> col+1 valid too
                rs[mt][0] += i0 + i1;
                rs[mt][1] += i2 + i3;
                float2 v01 = make_float2(i0, i1);
                float2 v23 = make_float2(i2, i3);
                *(float2*)(out + (size_t)mrow * C_COLS + col) = v01;
                *(float2*)(out + (size_t)(mrow + 8) * C_COLS + col) = v23;
            }
        }
    }
    // reduce row sums over the 4 lanes sharing a row (xor 1, 2), then atomics
#pragma unroll
    for (int mt = 0; mt < 4; mt++) {
#pragma unroll
        for (int h = 0; h < 2; h++) {
            float v = rs[mt][h];
            v += __shfl_xor_sync(0xffffffffu, v, 1);
            v += __shfl_xor_sync(0xffffffffu, v, 2);
            if ((l & 3) == 0) {
                int mrow = m0 + wm * 64 + mt * 16 + (l >> 2) + h * 8;
                atomicAdd(&g_rowsum[mrow], v);
            }
        }
    }
}

// ---------------------------------------------------------------------------
// Kernel 4: logits = -(iso + rowmean) / temperature, flat float4 grid.
// ---------------------------------------------------------------------------
#define F4_PER_ROW (C_COLS / 4)              // 250
#define FIN_TOTAL  (B_ROWS * F4_PER_ROW)     // 4,096,000

__global__ void __launch_bounds__(256) finalize_kernel(float* __restrict__ out,
                                                       const float* __restrict__ temp) {
    unsigned v = blockIdx.x * 256u + threadIdx.x;
    if (v >= (unsigned)FIN_TOTAL) return;
    unsigned row = v / (unsigned)F4_PER_ROW;
    float m = __ldg(&g_rowsum[row]) * (1.0f / (float)C_COLS);
    float invt = 1.0f / __ldg(temp);
    float4 x = *(float4*)(out + (size_t)v * 4);
    x.x = -(x.x + m) * invt;
    x.y = -(x.y + m) * invt;
    x.z = -(x.z + m) * invt;
    x.w = -(x.w + m) * invt;
    *(float4*)(out + (size_t)v * 4) = x;
}

// ---------------------------------------------------------------------------
extern "C" void kernel_launch(void* const* d_in, const int* in_sizes, int n_in,
                              void* d_out, int out_size) {
    const float* feat = (const float*)d_in[0];
    const float* prot = (const float*)d_in[1];
    const float* ds   = (const float*)d_in[2];
    const float* temp = (const float*)d_in[3];
    float* out = (float*)d_out;

    cudaFuncSetAttribute(gemm_kernel, cudaFuncAttributeMaxDynamicSharedMemorySize, GEMM_SMEM);

    norm_features_kernel<<<B_ROWS, 256>>>(feat);
    norm_protos_kernel<<<C_PAD, 256>>>(prot);
    gemm_kernel<<<dim3(C_PAD / 128, B_ROWS / 128), 256, GEMM_SMEM>>>(ds, out);
    finalize_kernel<<<(FIN_TOTAL + 255) / 256, 256>>>(out, temp);
}